// round 3
// baseline (speedup 1.0000x reference)
#include <cuda_runtime.h>

#define BB 1024
#define TT 2048
#define DD 16
#define UU 4
#define HH 128
#define MM 8
#define NT 512

typedef unsigned long long u64;

// ---- f32x2 helpers (packed-FMA path: PTX-only on sm_103a) ----
__device__ __forceinline__ u64 pk2(float lo, float hi) {
    u64 r; asm("mov.b64 %0, {%1, %2};" : "=l"(r) : "f"(lo), "f"(hi)); return r;
}
__device__ __forceinline__ void upk2(u64 v, float& lo, float& hi) {
    asm("mov.b64 {%0, %1}, %2;" : "=f"(lo), "=f"(hi) : "l"(v));
}
__device__ __forceinline__ u64 ffma2(u64 a, u64 b, u64 c) {
    u64 d; asm("fma.rn.f32x2 %0, %1, %2, %3;" : "=l"(d) : "l"(a), "l"(b), "l"(c)); return d;
}
__device__ __forceinline__ u64 add2(u64 a, u64 b) {
    u64 c; asm("add.rn.f32x2 %0, %1, %2;" : "=l"(c) : "l"(a), "l"(b)); return c;
}
__device__ __forceinline__ float tanh_fast(float x) {
    float y; asm("tanh.approx.f32 %0, %1;" : "=f"(y) : "f"(x)); return y;
}
__device__ __forceinline__ u64 shfl_xor64(u64 v, int mask) {
    unsigned lo = (unsigned)v, hi = (unsigned)(v >> 32);
    lo = __shfl_xor_sync(0xffffffffu, lo, mask);
    hi = __shfl_xor_sync(0xffffffffu, hi, mask);
    return ((u64)hi << 32) | (u64)lo;
}

// Shared layouts (all padded for single-wavefront access):
//  sW0d : u64[(D+U)*H]          duplicated W0 pairs, [k][j]         (20 KB)
//  sH1  : float[8 * 132]        8 k-slices of 16 k x 8 m, skew 132  (4.2 KB)
//  sH2  : float[8 * 144]        [m][kq2*36 + kk]                    (4.6 KB)
//  sIN  : float[(D+U) * 8]      [k][m]; rows 0..15=y, 16..19=x_t

__global__ void __launch_bounds__(NT, 1)
gnsde_kernel(const float* __restrict__ carry,
             const float* __restrict__ x,
             const float* __restrict__ noise,
             const float* __restrict__ W0,
             const float* __restrict__ b0,
             const float* __restrict__ W1,
             const float* __restrict__ b1,
             const float* __restrict__ W2,
             const float* __restrict__ b2,
             float* __restrict__ out)
{
    __shared__ __align__(16) u64   sW0d[(DD + UU) * HH];
    __shared__ __align__(16) float sH1[8 * 132];
    __shared__ __align__(16) float sH2[MM * 144];
    __shared__ __align__(16) float sIN[(DD + UU) * MM];

    const int tid = threadIdx.x;
    const int b0r = blockIdx.x * MM;

    // layer-0 identity: (j, m-pair)
    const int j0i = tid >> 2;
    const int mp0 = tid & 3;
    // layer-1 identity: (j-pair, k-octant)
    const int jp  = tid >> 3;
    const int kq  = tid & 7;
    // layer-2 identity: ((m,d), k-quarter)
    const int md  = tid >> 2;
    const int m2  = md >> 4;
    const int d2  = md & 15;
    const int kq2 = tid & 3;

    // ---- persistent registers ----
    float w1r0[16], w1r1[16];
#pragma unroll
    for (int kk = 0; kk < 16; ++kk) {
        w1r0[kk] = W1[(kq * 16 + kk) * HH + 2 * jp];
        w1r1[kk] = W1[(kq * 16 + kk) * HH + 2 * jp + 1];
    }
    u64 w2p[16];
#pragma unroll
    for (int i = 0; i < 16; ++i) {
        int k = kq2 * 32 + 2 * i;
        w2p[i] = pk2(W2[k * DD + d2], W2[(k + 1) * DD + d2]);
    }
    const float b0j = b0[j0i];
    const float b1v = b1[2 * jp + (kq >> 2)];
    const float b2v = b2[d2];
    float yreg = carry[(size_t)(b0r + m2) * DD + d2];

    // ---- stage shared ----
    for (int idx = tid; idx < (DD + UU) * HH; idx += NT) {
        float w = W0[idx];
        sW0d[idx] = pk2(w, w);
    }
    if (kq2 == 0) sIN[d2 * MM + m2] = yreg;
    if (tid >= 480 && tid < 480 + MM) {
        int m = tid - 480;
        float4 xv = *(const float4*)&x[((size_t)(b0r + m) * TT) * UU];
        sIN[(DD + 0) * MM + m] = xv.x;
        sIN[(DD + 1) * MM + m] = xv.y;
        sIN[(DD + 2) * MM + m] = xv.z;
        sIN[(DD + 3) * MM + m] = xv.w;
    }
    __syncthreads();

    const float alpha = 0.1f;
    const float onema = 0.9f;
    const float sqa   = 0.31622776601683794f;

    float* ys  = out;
    float* mts = out + (size_t)BB * TT * DD;
    float* mus = out + 2ull * BB * TT * DD;

    for (int t = 0; t < TT; ++t) {
        // ---- prefetch globals for this step ----
        float nz = 0.0f;
        if (kq2 == 0) nz = noise[((size_t)(b0r + m2) * TT + t) * DD + d2];
        float4 xn = make_float4(0.f, 0.f, 0.f, 0.f);
        const bool xp = (tid >= 480 && tid < 480 + MM) && (t + 1 < TT);
        if (xp) xn = *(const float4*)&x[((size_t)(b0r + (tid - 480)) * TT + (t + 1)) * UU];

        // ================= layer 0: thread (j0i, mp0), full k=20 =================
        {
            u64 acc = pk2(b0j, b0j);
#pragma unroll
            for (int k = 0; k < DD + UU; ++k) {
                u64 w = sW0d[k * HH + j0i];
                u64 h = *(const u64*)&sIN[k * MM + 2 * mp0];
                acc = ffma2(w, h, acc);
            }
            float lo, hi; upk2(acc, lo, hi);
            *(u64*)&sH1[(j0i >> 4) * 132 + (j0i & 15) * 8 + 2 * mp0] =
                pk2(tanh_fast(lo), tanh_fast(hi));
        }
        __syncthreads();

        // ================= layer 1: thread (jp, kq), k-slice of 16 =================
        {
            u64 a0 = 0, a1 = 0, a2 = 0, a3 = 0, a4 = 0, a5 = 0, a6 = 0, a7 = 0;
            const float* hbase = &sH1[kq * 132];
#pragma unroll
            for (int kk = 0; kk < 16; ++kk) {
                ulonglong2 hA = *(const ulonglong2*)&hbase[kk * 8];
                ulonglong2 hB = *(const ulonglong2*)&hbase[kk * 8 + 4];
                u64 wd0 = pk2(w1r0[kk], w1r0[kk]);
                u64 wd1 = pk2(w1r1[kk], w1r1[kk]);
                a0 = ffma2(wd0, hA.x, a0); a1 = ffma2(wd0, hA.y, a1);
                a2 = ffma2(wd0, hB.x, a2); a3 = ffma2(wd0, hB.y, a3);
                a4 = ffma2(wd1, hA.x, a4); a5 = ffma2(wd1, hA.y, a5);
                a6 = ffma2(wd1, hB.x, a6); a7 = ffma2(wd1, hB.y, a7);
            }
            // butterfly reduce with index-halving: lane kq ends with global sum g==kq
            // globals: g = jj*4 + mp  (a0..a3 = jj0, a4..a7 = jj1)
            const bool u4 = (kq & 4) != 0;
            u64 k0 = u4 ? a4 : a0, s0 = u4 ? a0 : a4;
            u64 k1 = u4 ? a5 : a1, s1 = u4 ? a1 : a5;
            u64 k2 = u4 ? a6 : a2, s2 = u4 ? a2 : a6;
            u64 k3 = u4 ? a7 : a3, s3 = u4 ? a3 : a7;
            u64 n0 = add2(k0, shfl_xor64(s0, 4));
            u64 n1 = add2(k1, shfl_xor64(s1, 4));
            u64 n2 = add2(k2, shfl_xor64(s2, 4));
            u64 n3 = add2(k3, shfl_xor64(s3, 4));
            const bool u2 = (kq & 2) != 0;
            u64 p0k = u2 ? n2 : n0, p0s = u2 ? n0 : n2;
            u64 p1k = u2 ? n3 : n1, p1s = u2 ? n1 : n3;
            u64 p0 = add2(p0k, shfl_xor64(p0s, 2));
            u64 p1 = add2(p1k, shfl_xor64(p1s, 2));
            const bool u1 = (kq & 1) != 0;
            u64 qk = u1 ? p1 : p0, qs = u1 ? p0 : p1;
            u64 tot = add2(qk, shfl_xor64(qs, 1));

            float lo, hi; upk2(tot, lo, hi);
            lo = tanh_fast(lo + b1v);
            hi = tanh_fast(hi + b1v);
            const int jw = 2 * jp + (kq >> 2);
            const int mA = 2 * (kq & 3);
            const int cw = (jw >> 5) * 36 + (jw & 31);
            sH2[mA * 144 + cw]       = lo;
            sH2[(mA + 1) * 144 + cw] = hi;
        }
        __syncthreads();

        // ================= layer 2 + gate: thread ((m2,d2), kq2) =================
        {
            u64 accA = 0, accB = 0;
            const float* h2b = &sH2[m2 * 144 + kq2 * 36];
#pragma unroll
            for (int i = 0; i < 8; ++i) {
                ulonglong2 hp = *(const ulonglong2*)&h2b[4 * i];
                accA = ffma2(hp.x, w2p[2 * i],     accA);
                accB = ffma2(hp.y, w2p[2 * i + 1], accB);
            }
            u64 acc = add2(accA, accB);
            acc = add2(acc, shfl_xor64(acc, 1));
            acc = add2(acc, shfl_xor64(acc, 2));
            if (kq2 == 0) {
                float lo, hi; upk2(acc, lo, hi);
                float mt = lo + hi + b2v;
                float mu = onema * yreg + alpha * mt;
                float yn = mu + sqa * nz;
                size_t base = ((size_t)(b0r + m2) * TT + t) * DD + d2;
                ys[base]  = yn;
                mts[base] = mt;
                mus[base] = mu;
                yreg = yn;
                sIN[d2 * MM + m2] = yn;
            }
            if (xp) {
                int m = tid - 480;
                sIN[(DD + 0) * MM + m] = xn.x;
                sIN[(DD + 1) * MM + m] = xn.y;
                sIN[(DD + 2) * MM + m] = xn.z;
                sIN[(DD + 3) * MM + m] = xn.w;
            }
        }
        __syncthreads();
    }
}

extern "C" void kernel_launch(void* const* d_in, const int* in_sizes, int n_in,
                              void* d_out, int out_size) {
    const float* carry = (const float*)d_in[0];
    const float* x     = (const float*)d_in[1];
    const float* noise = (const float*)d_in[2];
    const float* W0    = (const float*)d_in[3];
    const float* b0    = (const float*)d_in[4];
    const float* W1    = (const float*)d_in[5];
    const float* b1    = (const float*)d_in[6];
    const float* W2    = (const float*)d_in[7];
    const float* b2    = (const float*)d_in[8];
    float* out = (float*)d_out;

    gnsde_kernel<<<BB / MM, NT>>>(carry, x, noise, W0, b0, W1, b1, W2, b2, out);
}

// round 4
// speedup vs baseline: 1.7223x; 1.7223x over previous
#include <cuda_runtime.h>

#define BB 1024
#define TT 2048
#define DD 16
#define UU 4
#define HH 128
#define MM 8
#define NT 512
#define INP 28          // sINt row pitch (floats): distinct banks per row, 16B-aligned
#define H2P 132         // sH1/sH2/sW2T row pitch

typedef unsigned long long u64;

__device__ __forceinline__ u64 pk2(float lo, float hi) {
    u64 r; asm("mov.b64 %0, {%1, %2};" : "=l"(r) : "f"(lo), "f"(hi)); return r;
}
__device__ __forceinline__ void upk2(u64 v, float& lo, float& hi) {
    asm("mov.b64 {%0, %1}, %2;" : "=f"(lo), "=f"(hi) : "l"(v));
}
__device__ __forceinline__ u64 ffma2(u64 a, u64 b, u64 c) {
    u64 d; asm("fma.rn.f32x2 %0, %1, %2, %3;" : "=l"(d) : "l"(a), "l"(b), "l"(c)); return d;
}
__device__ __forceinline__ u64 add2(u64 a, u64 b) {
    u64 c; asm("add.rn.f32x2 %0, %1, %2;" : "=l"(c) : "l"(a), "l"(b)); return c;
}
__device__ __forceinline__ float tanh_fast(float x) {
    float y; asm("tanh.approx.f32 %0, %1;" : "=f"(y) : "f"(x)); return y;
}
__device__ __forceinline__ u64 shfl_xor64(u64 v, int mask) {
    unsigned lo = (unsigned)v, hi = (unsigned)(v >> 32);
    lo = __shfl_xor_sync(0xffffffffu, lo, mask);
    hi = __shfl_xor_sync(0xffffffffu, hi, mask);
    return ((u64)hi << 32) | (u64)lo;
}

__global__ void __launch_bounds__(NT, 1)
gnsde_kernel(const float* __restrict__ carry,
             const float* __restrict__ x,
             const float* __restrict__ noise,
             const float* __restrict__ W0,
             const float* __restrict__ b0,
             const float* __restrict__ W1,
             const float* __restrict__ b1,
             const float* __restrict__ W2,
             const float* __restrict__ b2,
             float* __restrict__ out)
{
    __shared__ __align__(16) float sH1[8 * H2P];        // k-sliced h1: [k>>4][ (k&15)*8 + m ]
    __shared__ __align__(16) float sH2[MM * H2P];       // [m][j], pitch 132
    __shared__ __align__(16) float sW2T[DD * H2P];      // [d][k], pitch 132
    __shared__ __align__(16) float sINt[MM * INP];      // [m][k]: k 0..15 = y, 16..19 = x_t
    __shared__ float               sb2[DD];

    const int tid = threadIdx.x;
    const int b0r = blockIdx.x * MM;

    // layer-0 identity: (j0, m-pair)
    const int j0  = tid >> 2;
    const int mp0 = tid & 3;
    // layer-1 identity: (j-pair, k-octant) -- efficient warp interleave
    const int jp  = tid >> 3;
    const int kq  = tid & 7;
    // layer-2 identity (tid < 128): (m2, d2)
    const int m2  = (tid >> 4) & 7;
    const int d2  = tid & 15;

    // ---- persistent registers ----
    u64 w0p[(DD + UU) / 2];
#pragma unroll
    for (int i = 0; i < (DD + UU) / 2; ++i)
        w0p[i] = pk2(W0[(2 * i) * HH + j0], W0[(2 * i + 1) * HH + j0]);
    float w1r0[16], w1r1[16];
#pragma unroll
    for (int kk = 0; kk < 16; ++kk) {
        w1r0[kk] = W1[(kq * 16 + kk) * HH + 2 * jp];
        w1r1[kk] = W1[(kq * 16 + kk) * HH + 2 * jp + 1];
    }
    const float b0j = b0[j0];
    const float b1v = b1[2 * jp + (kq >> 2)];

    // ---- stage shared ----
    for (int idx = tid; idx < HH * DD; idx += NT) {
        int i = idx >> 4, d = idx & 15;
        sW2T[d * H2P + i] = W2[idx];     // W2 is [H][D] row-major
    }
    if (tid < DD) sb2[tid] = b2[tid];

    float yreg = 0.0f;
    if (tid < 128) {
        yreg = carry[(size_t)(b0r + m2) * DD + d2];
        sINt[m2 * INP + d2] = yreg;
    }
    if (tid >= 480 && tid < 480 + MM) {
        int m = tid - 480;
        float4 xv = *(const float4*)&x[((size_t)(b0r + m) * TT) * UU];
        *(float4*)&sINt[m * INP + DD] = xv;
    }
    __syncthreads();

    const float alpha = 0.1f;
    const float onema = 0.9f;
    const float sqa   = 0.31622776601683794f;

    float* ys  = out;
    float* mts = out + (size_t)BB * TT * DD;
    float* mus = out + 2ull * BB * TT * DD;

    for (int t = 0; t < TT; ++t) {
        // ---- prefetch globals for this step ----
        float nz = 0.0f;
        if (tid < 128) nz = noise[((size_t)(b0r + m2) * TT + t) * DD + d2];
        float4 xn = make_float4(0.f, 0.f, 0.f, 0.f);
        const bool xp = (tid >= 480 && tid < 480 + MM) && (t + 1 < TT);
        if (xp) xn = *(const float4*)&x[((size_t)(b0r + (tid - 480)) * TT + (t + 1)) * UU];

        // ===== layer 0: thread (j0, mp0); dense k-reads from sINt rows =====
        {
            u64 aA0 = 0, aA1 = 0, aB0 = 0, aB1 = 0;
            const float* r0p = &sINt[(2 * mp0) * INP];
            const float* r1p = &sINt[(2 * mp0 + 1) * INP];
#pragma unroll
            for (int i = 0; i < 5; ++i) {
                ulonglong2 hA = *(const ulonglong2*)&r0p[4 * i];
                ulonglong2 hB = *(const ulonglong2*)&r1p[4 * i];
                aA0 = ffma2(w0p[2 * i],     hA.x, aA0);
                aA1 = ffma2(w0p[2 * i + 1], hA.y, aA1);
                aB0 = ffma2(w0p[2 * i],     hB.x, aB0);
                aB1 = ffma2(w0p[2 * i + 1], hB.y, aB1);
            }
            float lA, hA2; upk2(add2(aA0, aA1), lA, hA2);
            float lB, hB2; upk2(add2(aB0, aB1), lB, hB2);
            float v0 = tanh_fast(lA + hA2 + b0j);
            float v1 = tanh_fast(lB + hB2 + b0j);
            *(u64*)&sH1[(j0 >> 4) * H2P + (j0 & 15) * 8 + 2 * mp0] = pk2(v0, v1);
        }
        __syncthreads();

        // ===== layer 1: thread (jp, kq); W1 in regs, dense act wavefronts =====
        {
            u64 a0 = 0, a1 = 0, a2 = 0, a3 = 0, a4 = 0, a5 = 0, a6 = 0, a7 = 0;
            const float* hbase = &sH1[kq * H2P];
#pragma unroll
            for (int kk = 0; kk < 16; ++kk) {
                ulonglong2 hA = *(const ulonglong2*)&hbase[kk * 8];
                ulonglong2 hB = *(const ulonglong2*)&hbase[kk * 8 + 4];
                u64 wd0 = pk2(w1r0[kk], w1r0[kk]);
                u64 wd1 = pk2(w1r1[kk], w1r1[kk]);
                a0 = ffma2(wd0, hA.x, a0); a1 = ffma2(wd0, hA.y, a1);
                a2 = ffma2(wd0, hB.x, a2); a3 = ffma2(wd0, hB.y, a3);
                a4 = ffma2(wd1, hA.x, a4); a5 = ffma2(wd1, hA.y, a5);
                a6 = ffma2(wd1, hB.x, a6); a7 = ffma2(wd1, hB.y, a7);
            }
            // butterfly reduce with index-halving over the 8-way k-split
            const bool u4 = (kq & 4) != 0;
            u64 k0 = u4 ? a4 : a0, s0 = u4 ? a0 : a4;
            u64 k1 = u4 ? a5 : a1, s1 = u4 ? a1 : a5;
            u64 k2 = u4 ? a6 : a2, s2 = u4 ? a2 : a6;
            u64 k3 = u4 ? a7 : a3, s3 = u4 ? a3 : a7;
            u64 n0 = add2(k0, shfl_xor64(s0, 4));
            u64 n1 = add2(k1, shfl_xor64(s1, 4));
            u64 n2 = add2(k2, shfl_xor64(s2, 4));
            u64 n3 = add2(k3, shfl_xor64(s3, 4));
            const bool u2 = (kq & 2) != 0;
            u64 p0k = u2 ? n2 : n0, p0s = u2 ? n0 : n2;
            u64 p1k = u2 ? n3 : n1, p1s = u2 ? n1 : n3;
            u64 p0 = add2(p0k, shfl_xor64(p0s, 2));
            u64 p1 = add2(p1k, shfl_xor64(p1s, 2));
            const bool u1 = (kq & 1) != 0;
            u64 qk = u1 ? p1 : p0, qs = u1 ? p0 : p1;
            u64 tot = add2(qk, shfl_xor64(qs, 1));

            float lo, hi; upk2(tot, lo, hi);
            lo = tanh_fast(lo + b1v);
            hi = tanh_fast(hi + b1v);
            const int jw = 2 * jp + (kq >> 2);
            const int mA = 2 * (kq & 3);
            sH2[mA * H2P + jw]       = lo;
            sH2[(mA + 1) * H2P + jw] = hi;
        }
        __syncthreads();

        // ===== layer 2 + gate + noise: threads 0..127 = (m2, d2) =====
        if (tid < 128) {
            u64 accA = 0, accB = 0;
            const float* hrow = &sH2[m2 * H2P];
            const float* wrow = &sW2T[d2 * H2P];
#pragma unroll
            for (int i = 0; i < HH / 4; ++i) {
                ulonglong2 hp = *(const ulonglong2*)&hrow[4 * i];
                ulonglong2 wp = *(const ulonglong2*)&wrow[4 * i];
                accA = ffma2(hp.x, wp.x, accA);
                accB = ffma2(hp.y, wp.y, accB);
            }
            float lo, hi; upk2(add2(accA, accB), lo, hi);
            float mt = lo + hi + sb2[d2];
            float mu = onema * yreg + alpha * mt;
            float yn = mu + sqa * nz;

            size_t base = ((size_t)(b0r + m2) * TT + t) * DD + d2;
            ys[base]  = yn;
            mts[base] = mt;
            mus[base] = mu;

            yreg = yn;
            sINt[m2 * INP + d2] = yn;      // publish y for next step
        } else if (xp) {
            int m = tid - 480;
            *(float4*)&sINt[m * INP + DD] = xn;
        }
        __syncthreads();
    }
}

extern "C" void kernel_launch(void* const* d_in, const int* in_sizes, int n_in,
                              void* d_out, int out_size) {
    const float* carry = (const float*)d_in[0];
    const float* x     = (const float*)d_in[1];
    const float* noise = (const float*)d_in[2];
    const float* W0    = (const float*)d_in[3];
    const float* b0    = (const float*)d_in[4];
    const float* W1    = (const float*)d_in[5];
    const float* b1    = (const float*)d_in[6];
    const float* W2    = (const float*)d_in[7];
    const float* b2    = (const float*)d_in[8];
    float* out = (float*)d_out;

    gnsde_kernel<<<BB / MM, NT>>>(carry, x, noise, W0, b0, W1, b1, W2, b2, out);
}